// round 7
// baseline (speedup 1.0000x reference)
#include <cuda_runtime.h>

#define NN 50000
#define NE 800000
#define NF 256
#define NH 64
#define NC 40
#define EPSR 0.3f
#define NB_SCAN ((NN + 255) / 256)   // 196
#define MT 64                         // gemm M-tile
#define KT 32                         // gemm K-chunk
#define AGG_WPB 16                    // warps (nodes) per agg block

// ---- device scratch ----
__device__ __align__(128) int   g_deg[NN];
__device__ __align__(128) int   g_cnt[NN];
__device__ __align__(128) int   g_fill[NN];
__device__ __align__(128) float g_ci[NN];         // nd[n]/max(cnt,1)
__device__ __align__(128) float g_s2[NN];
__device__ __align__(128) float g_snA[2 * NN];    // {s1_layer0, nd}
__device__ __align__(128) float g_snB[2 * NN];    // {s1_layer1, nd}
__device__ __align__(128) int   g_ptr[NN + 1];
__device__ __align__(128) int   g_bsum[NB_SCAN];
__device__ __align__(128) int   g_srcA[NE];
__device__ __align__(128) float g_h[NN * NH];     // layer-0 h == raw
__device__ __align__(128) float g_h2[NN * NH];
__device__ __align__(128) float g_W1t[NF * NH];

__global__ void k_zero() {
    int i = blockIdx.x * blockDim.x + threadIdx.x;
    if (i < NN) { g_deg[i] = 0; g_cnt[i] = 0; }
}

__global__ void k_w1t(const float* __restrict__ W1) {
    int i = blockIdx.x * blockDim.x + threadIdx.x;
    if (i < NF * NH) {
        int k = i >> 6, j = i & 63;
        g_W1t[i] = W1[j * NF + k];
    }
}

// 2 edges per thread, int2 loads
__global__ void k_count(const int* __restrict__ ei) {
    int t = blockIdx.x * blockDim.x + threadIdx.x;
    if (t >= NE / 2) return;
    int2 r2 = ((const int2*)ei)[t];
    int2 c2 = ((const int2*)(ei + NE))[t];
    atomicAdd(&g_deg[r2.x], 1);
    atomicAdd(&g_deg[r2.y], 1);
    atomicAdd(&g_cnt[c2.x], 1);
    atomicAdd(&g_cnt[c2.y], 1);
}

// block scan of cnt + node prep fused
__global__ void k_scan1() {
    __shared__ int sh[256];
    int i = blockIdx.x * 256 + threadIdx.x;
    int v = (i < NN) ? g_cnt[i] : 0;
    sh[threadIdx.x] = v;
    __syncthreads();
    for (int off = 1; off < 256; off <<= 1) {
        int t = (threadIdx.x >= off) ? sh[threadIdx.x - off] : 0;
        __syncthreads();
        sh[threadIdx.x] += t;
        __syncthreads();
    }
    if (i < NN) {
        g_ptr[i] = sh[threadIdx.x] - v;
        int d = g_deg[i]; if (d < 1) d = 1;
        float nd = rsqrtf((float)d);
        int c = v; if (c < 1) c = 1;
        g_ci[i] = nd / (float)c;
        g_snA[2 * i + 1] = nd;
        g_snB[2 * i + 1] = nd;
    }
    if (threadIdx.x == 255) g_bsum[blockIdx.x] = sh[255];
}

__global__ void k_scan2() {
    __shared__ int sh[256];
    int i = threadIdx.x;
    int v = (i < NB_SCAN) ? g_bsum[i] : 0;
    sh[i] = v;
    __syncthreads();
    for (int off = 1; off < 256; off <<= 1) {
        int t = (i >= off) ? sh[i - off] : 0;
        __syncthreads();
        sh[i] += t;
        __syncthreads();
    }
    if (i < NB_SCAN) g_bsum[i] = sh[i] - v;
}

__global__ void k_scan3() {
    int i = blockIdx.x * 256 + threadIdx.x;
    if (i < NN) {
        int v = g_ptr[i] + g_bsum[blockIdx.x];
        g_ptr[i]  = v;
        g_fill[i] = v;
    }
    if (i == 0) g_ptr[NN] = NE;
}

// CSR bucketing: 2 edges per thread, int2 loads
__global__ void k_bucket(const int* __restrict__ ei) {
    int t = blockIdx.x * blockDim.x + threadIdx.x;
    if (t >= NE / 2) return;
    int2 r2 = ((const int2*)ei)[t];
    int2 c2 = ((const int2*)(ei + NE))[t];
    int p0 = atomicAdd(&g_fill[c2.x], 1);
    int p1 = atomicAdd(&g_fill[c2.y], 1);
    g_srcA[p0] = r2.x;
    g_srcA[p1] = r2.y;
}

// Tiled GEMM: h = relu(x @ W1^T + b1); epilogue: layer-0 gate scalars.
__global__ __launch_bounds__(256) void k_gemm1(const float* __restrict__ x,
                                               const float* __restrict__ b1,
                                               const float* __restrict__ gw) {
    __shared__ float xs[KT][MT + 4];
    __shared__ float ws[KT * NH];

    int tid = threadIdx.x;
    int tx = tid & 15;
    int ty = tid >> 4;
    int nb = blockIdx.x * MT;

    float acc[4][4] = {{0}};

    int lm = tid >> 2;
    int kq = tid & 3;
    int xrow = nb + lm; if (xrow >= NN) xrow = NN - 1;
    const float* xr = x + (size_t)xrow * NF;

    for (int k0 = 0; k0 < NF; k0 += KT) {
        float4 a0 = *(const float4*)(xr + k0 + kq * 8);
        float4 a1 = *(const float4*)(xr + k0 + kq * 8 + 4);
        xs[kq * 8 + 0][lm] = a0.x; xs[kq * 8 + 1][lm] = a0.y;
        xs[kq * 8 + 2][lm] = a0.z; xs[kq * 8 + 3][lm] = a0.w;
        xs[kq * 8 + 4][lm] = a1.x; xs[kq * 8 + 5][lm] = a1.y;
        xs[kq * 8 + 6][lm] = a1.z; xs[kq * 8 + 7][lm] = a1.w;
        const float4* wsrc = (const float4*)(g_W1t + k0 * NH);
        float4* wdst = (float4*)ws;
        wdst[tid]       = wsrc[tid];
        wdst[tid + 256] = wsrc[tid + 256];
        __syncthreads();
#pragma unroll
        for (int kk = 0; kk < KT; kk++) {
            float4 av = *(const float4*)&xs[kk][ty * 4];
            float4 bv = *(const float4*)&ws[kk * NH + tx * 4];
            acc[0][0] += av.x * bv.x; acc[0][1] += av.x * bv.y;
            acc[0][2] += av.x * bv.z; acc[0][3] += av.x * bv.w;
            acc[1][0] += av.y * bv.x; acc[1][1] += av.y * bv.y;
            acc[1][2] += av.y * bv.z; acc[1][3] += av.y * bv.w;
            acc[2][0] += av.z * bv.x; acc[2][1] += av.z * bv.y;
            acc[2][2] += av.z * bv.z; acc[2][3] += av.z * bv.w;
            acc[3][0] += av.w * bv.x; acc[3][1] += av.w * bv.y;
            acc[3][2] += av.w * bv.z; acc[3][3] += av.w * bv.w;
        }
        __syncthreads();
    }

    float4 bb = *(const float4*)(b1 + tx * 4);
    float4 wa = *(const float4*)(gw + tx * 4);
    float4 wb = *(const float4*)(gw + NH + tx * 4);

    float (*s1p)[17] = (float(*)[17])&xs[0][0];
    float (*s2p)[17] = (float(*)[17])&ws[0];

#pragma unroll
    for (int i = 0; i < 4; i++) {
        int n = nb + ty * 4 + i;
        float4 hv;
        hv.x = fmaxf(acc[i][0] + bb.x, 0.0f);
        hv.y = fmaxf(acc[i][1] + bb.y, 0.0f);
        hv.z = fmaxf(acc[i][2] + bb.z, 0.0f);
        hv.w = fmaxf(acc[i][3] + bb.w, 0.0f);
        if (n < NN) *(float4*)(g_h + n * NH + tx * 4) = hv;
        s1p[ty * 4 + i][tx] = hv.x * wa.x + hv.y * wa.y + hv.z * wa.z + hv.w * wa.w;
        s2p[ty * 4 + i][tx] = hv.x * wb.x + hv.y * wb.y + hv.z * wb.z + hv.w * wb.w;
    }
    __syncthreads();
    if (tid < MT) {
        int n = nb + tid;
        if (n < NN) {
            float s1 = 0.0f, s2 = 0.0f;
#pragma unroll
            for (int q = 0; q < 16; q++) { s1 += s1p[tid][q]; s2 += s2p[tid][q]; }
            g_snA[2 * n] = s1;
            g_s2[n] = s2;
        }
    }
}

// 8-wide unrolled gather body (shared by both agg kernels)
#define AGG_GATHER_LOOP(HSRC)                                                    \
    int cnt = e - base; if (cnt > 32) cnt = 32;                                  \
    int ii = 0;                                                                  \
    for (; ii + 8 <= cnt; ii += 8) {                                             \
        int   r0 = s_src[w][ii    ], r1 = s_src[w][ii + 1];                      \
        int   r2 = s_src[w][ii + 2], r3 = s_src[w][ii + 3];                      \
        int   r4 = s_src[w][ii + 4], r5 = s_src[w][ii + 5];                      \
        int   r6 = s_src[w][ii + 6], r7 = s_src[w][ii + 7];                      \
        float n0 = s_nrm[w][ii    ], n1 = s_nrm[w][ii + 1];                      \
        float n2 = s_nrm[w][ii + 2], n3 = s_nrm[w][ii + 3];                      \
        float n4 = s_nrm[w][ii + 4], n5 = s_nrm[w][ii + 5];                      \
        float n6 = s_nrm[w][ii + 6], n7 = s_nrm[w][ii + 7];                      \
        float2 h0 = *(const float2*)(HSRC + r0 * NH + j2);                       \
        float2 h1 = *(const float2*)(HSRC + r1 * NH + j2);                       \
        float2 h2 = *(const float2*)(HSRC + r2 * NH + j2);                       \
        float2 h3 = *(const float2*)(HSRC + r3 * NH + j2);                       \
        float2 h4 = *(const float2*)(HSRC + r4 * NH + j2);                       \
        float2 h5 = *(const float2*)(HSRC + r5 * NH + j2);                       \
        float2 h6 = *(const float2*)(HSRC + r6 * NH + j2);                       \
        float2 h7 = *(const float2*)(HSRC + r7 * NH + j2);                       \
        acc.x += n0 * h0.x + n1 * h1.x + n2 * h2.x + n3 * h3.x                   \
               + n4 * h4.x + n5 * h5.x + n6 * h6.x + n7 * h7.x;                  \
        acc.y += n0 * h0.y + n1 * h1.y + n2 * h2.y + n3 * h3.y                   \
               + n4 * h4.y + n5 * h5.y + n6 * h6.y + n7 * h7.y;                  \
        ns    += n0 + n1 + n2 + n3 + n4 + n5 + n6 + n7;                          \
    }                                                                            \
    for (; ii < cnt; ii++) {                                                     \
        int   rr = s_src[w][ii];                                                 \
        float nn = s_nrm[w][ii];                                                 \
        float2 hh = *(const float2*)(HSRC + rr * NH + j2);                       \
        acc.x += nn * hh.x;                                                      \
        acc.y += nn * hh.y;                                                      \
        ns    += nn;                                                             \
    }

// layer-0 aggregation (warp per node) + layer-1 gate scalars into B buffers
__global__ __launch_bounds__(32 * AGG_WPB) void k_agg0(const float* __restrict__ gw_next,
                                                       const float* __restrict__ gb) {
    __shared__ int   s_src[AGG_WPB][32];
    __shared__ float s_nrm[AGG_WPB][32];
    int w    = threadIdx.x >> 5;
    int lane = threadIdx.x & 31;
    int n    = blockIdx.x * AGG_WPB + w;
    if (n >= NN) return;

    int b = g_ptr[n];
    int e = g_ptr[n + 1];
    float s2n = g_s2[n] + gb[0];
    float2 acc = make_float2(0.0f, 0.0f);
    float  ns  = 0.0f;
    int j2 = lane * 2;

    for (int base = b; base < e; base += 32) {
        int p = base + lane;
        int r = 0; float nm = 0.0f;
        if (p < e) {
            r = g_srcA[p];
            float2 sn = *(const float2*)(g_snA + 2 * r);
            nm = tanhf(sn.x + s2n) * sn.y;
        }
        s_src[w][lane] = r;
        s_nrm[w][lane] = nm;
        __syncwarp();
        AGG_GATHER_LOOP(g_h)
        __syncwarp();
    }

    float2 hself = *(const float2*)(g_h + n * NH + j2);
    float ci = g_ci[n];
    float2 ho;
    ho.x = EPSR * hself.x + (acc.x + hself.x * ns) * ci;
    ho.y = EPSR * hself.y + (acc.y + hself.y * ns) * ci;
    *(float2*)(g_h2 + n * NH + j2) = ho;

    float p1 = ho.x * gw_next[j2] + ho.y * gw_next[j2 + 1];
    float p2 = ho.x * gw_next[NH + j2] + ho.y * gw_next[NH + j2 + 1];
#pragma unroll
    for (int off = 16; off > 0; off >>= 1) {
        p1 += __shfl_xor_sync(0xffffffff, p1, off);
        p2 += __shfl_xor_sync(0xffffffff, p2, off);
    }
    if (lane == 0) { g_snB[2 * n] = p1; g_s2[n] = p2; }
}

// layer-1 aggregation fused with classifier + log_softmax
__global__ __launch_bounds__(32 * AGG_WPB) void k_agg1_out(const float* __restrict__ gb,
                                                           const float* __restrict__ W2,
                                                           const float* __restrict__ b2,
                                                           float* __restrict__ out) {
    __shared__ int   s_src[AGG_WPB][32];
    __shared__ float s_nrm[AGG_WPB][32];
    __shared__ float s_h[AGG_WPB][NH];
    __shared__ float sW2t[NH * NC];
    __shared__ float sb2[NC];

    int tid  = threadIdx.x;
    int w    = tid >> 5;
    int lane = tid & 31;
    int n    = blockIdx.x * AGG_WPB + w;

    for (int idx = tid; idx < NC * NH; idx += 32 * AGG_WPB) {
        int c = idx >> 6, j = idx & 63;
        sW2t[j * NC + c] = W2[idx];
    }
    if (tid < NC) sb2[tid] = b2[tid];
    __syncthreads();
    if (n >= NN) return;

    int b = g_ptr[n];
    int e = g_ptr[n + 1];
    float s2n = g_s2[n] + gb[1];
    float2 acc = make_float2(0.0f, 0.0f);
    float  ns  = 0.0f;
    int j2 = lane * 2;

    for (int base = b; base < e; base += 32) {
        int p = base + lane;
        int r = 0; float nm = 0.0f;
        if (p < e) {
            r = g_srcA[p];
            float2 sn = *(const float2*)(g_snB + 2 * r);
            nm = tanhf(sn.x + s2n) * sn.y;
        }
        s_src[w][lane] = r;
        s_nrm[w][lane] = nm;
        __syncwarp();
        AGG_GATHER_LOOP(g_h2)
        __syncwarp();
    }

    float2 hself = *(const float2*)(g_h2 + n * NH + j2);
    float2 rawv  = *(const float2*)(g_h  + n * NH + j2);
    float ci = g_ci[n];
    float2 ho;
    ho.x = EPSR * rawv.x + (acc.x + hself.x * ns) * ci;
    ho.y = EPSR * rawv.y + (acc.y + hself.y * ns) * ci;
    s_h[w][j2]     = ho.x;
    s_h[w][j2 + 1] = ho.y;
    __syncwarp();

    int c0 = lane;
    int c1 = lane + 32;
    float l0 = sb2[c0];
    float l1 = (c1 < NC) ? sb2[c1] : -3.0e38f;
#pragma unroll 8
    for (int j = 0; j < NH; j++) {
        float hv = s_h[w][j];
        l0 += hv * sW2t[j * NC + c0];
        if (c1 < NC) l1 += hv * sW2t[j * NC + c1];
    }
    float m = fmaxf(l0, l1);
#pragma unroll
    for (int off = 16; off > 0; off >>= 1)
        m = fmaxf(m, __shfl_xor_sync(0xffffffff, m, off));
    float s = expf(l0 - m) + ((c1 < NC) ? expf(l1 - m) : 0.0f);
#pragma unroll
    for (int off = 16; off > 0; off >>= 1)
        s += __shfl_xor_sync(0xffffffff, s, off);
    float lse = m + logf(s);
    float* o = out + (size_t)n * NC;
    o[c0] = l0 - lse;
    if (c1 < NC) o[c1] = l1 - lse;
}

extern "C" void kernel_launch(void* const* d_in, const int* in_sizes, int n_in,
                              void* d_out, int out_size) {
    const float* x  = (const float*)d_in[0];
    const int*   ei = (const int*)d_in[1];
    const float* W1 = (const float*)d_in[2];
    const float* b1 = (const float*)d_in[3];
    const float* W2 = (const float*)d_in[4];
    const float* b2 = (const float*)d_in[5];
    const float* gw = (const float*)d_in[6];
    const float* gb = (const float*)d_in[7];
    float* out = (float*)d_out;

    static cudaStream_t sB = nullptr;
    static cudaEvent_t evRoot = nullptr, evJoin = nullptr;
    if (!sB) {
        cudaStreamCreateWithFlags(&sB, cudaStreamNonBlocking);
        cudaEventCreateWithFlags(&evRoot, cudaEventDisableTiming);
        cudaEventCreateWithFlags(&evJoin, cudaEventDisableTiming);
    }

    const int B = 256;

    cudaEventRecord(evRoot, 0);
    cudaStreamWaitEvent(sB, evRoot, 0);
    k_w1t<<<(NF * NH + B - 1) / B, B, 0, sB>>>(W1);
    k_gemm1<<<(NN + MT - 1) / MT, 256, 0, sB>>>(x, b1, gw);
    cudaEventRecord(evJoin, sB);

    k_zero<<<(NN + B - 1) / B, B>>>();
    k_count<<<(NE / 2 + B - 1) / B, B>>>(ei);
    k_scan1<<<NB_SCAN, 256>>>();
    k_scan2<<<1, 256>>>();
    k_scan3<<<NB_SCAN, 256>>>();
    k_bucket<<<(NE / 2 + B - 1) / B, B>>>(ei);

    cudaStreamWaitEvent(0, evJoin, 0);

    k_agg0<<<(NN + AGG_WPB - 1) / AGG_WPB, 32 * AGG_WPB>>>(gw + 2 * NH, gb);
    k_agg1_out<<<(NN + AGG_WPB - 1) / AGG_WPB, 32 * AGG_WPB>>>(gb, W2, b2, out);
}